// round 15
// baseline (speedup 1.0000x reference)
#include <cuda_runtime.h>
#include <cuda_bf16.h>
#include <math.h>
#include <stdint.h>

#define BATCH 1024

// ---------------- scratch (static device globals; no allocs allowed) ----------------
__device__ float g_p1[BATCH*32*16*16];   // conv1+maxpool out
__device__ float g_p2[BATCH*64*8*8];     // conv2+maxpool out
__device__ float g_flat[BATCH*2048];     // conv3+avgpool out (flatten)
__device__ float g_fc1[BATCH*512];       // fc1 out
// fragment-ordered conv weights (bf16x2 hi/lo, SoA)
__device__ uint4 g_wf1h[2*2*32];
__device__ uint4 g_wf1l[2*2*32];
__device__ uint4 g_wf2h[4*18*32];
__device__ uint4 g_wf2l[4*18*32];
__device__ uint4 g_wf3h[8*36*32];
__device__ uint4 g_wf3l[8*36*32];

static const float INVBN = 0.9999950000374998f; // 1/sqrt(1+1e-5)

__device__ __forceinline__ float warp_sum(float v) {
#pragma unroll
    for (int o = 16; o > 0; o >>= 1) v += __shfl_xor_sync(0xffffffffu, v, o);
    return v;
}
__device__ __forceinline__ float warp_max(float v) {
#pragma unroll
    for (int o = 16; o > 0; o >>= 1) v = fmaxf(v, __shfl_xor_sync(0xffffffffu, v, o));
    return v;
}

// pack two floats to bf16x2: low half = v0, high half = v1
__device__ __forceinline__ uint32_t pk_bf16x2(float lo, float hi) {
    uint32_t r; asm("cvt.rn.bf16x2.f32 %0, %1, %2;" : "=r"(r) : "f"(hi), "f"(lo)); return r;
}
__device__ __forceinline__ uint2 split_bf16_pair(float v0, float v1) {
    uint32_t h = pk_bf16x2(v0, v1);
    float h0 = __uint_as_float(h << 16);
    float h1 = __uint_as_float(h & 0xffff0000u);
    uint32_t l = pk_bf16x2(v0 - h0, v1 - h1);
    return make_uint2(h, l);
}

#define MMA_BF16(Cv, Aa, Bb) \
    asm volatile("mma.sync.aligned.m16n8k16.row.col.f32.bf16.bf16.f32 " \
                 "{%0,%1,%2,%3},{%4,%5,%6,%7},{%8,%9},{%0,%1,%2,%3};" \
                 : "+f"((Cv)[0]), "+f"((Cv)[1]), "+f"((Cv)[2]), "+f"((Cv)[3]) \
                 : "r"((Aa)[0]), "r"((Aa)[1]), "r"((Aa)[2]), "r"((Aa)[3]), \
                   "r"((Bb)[0]), "r"((Bb)[1]))

// ---------------- weight pre-split (chunked convs: K = 16 channels per tap) ----------
template<int CIN, int COUT>
__global__ void wsplit_frag_kernel(const float* __restrict__ wgt,
                                   uint4* __restrict__ WH, uint4* __restrict__ WL)
{
    constexpr int S_TOT = (CIN / 16) * 9;
    int i = blockIdx.x * 256 + threadIdx.x;
    if (i >= (COUT / 16) * S_TOT * 32) return;
    int lane = i & 31;
    int g = (i >> 5) % S_TOT;
    int mtile = (i >> 5) / S_TOT;
    int gID = lane >> 2, qID = lane & 3;
    int cc = g / 9, s = g % 9;
    uint32_t h[4], l[4];
#pragma unroll
    for (int e = 0; e < 4; e++) {
        int m = mtile * 16 + gID + 8 * (e & 1);
        int kpair = qID + 4 * (e >> 1);
        int ci0 = cc * 16 + 2 * kpair;
        float w0 = wgt[(m * CIN + ci0) * 9 + s];
        float w1 = wgt[(m * CIN + ci0 + 1) * 9 + s];
        uint2 sp = split_bf16_pair(w0, w1);
        h[e] = sp.x; l[e] = sp.y;
    }
    WH[i] = make_uint4(h[0], h[1], h[2], h[3]);
    WL[i] = make_uint4(l[0], l[1], l[2], l[3]);
}

// ---------------- conv1 weight pre-split: K = ci*9+tap (27, padded to 32) ------------
__global__ void wsplit_conv1(const float* __restrict__ wgt,
                             uint4* __restrict__ WH, uint4* __restrict__ WL)
{
    int i = threadIdx.x;  // 128 threads: [mtile(2)][kstep(2)][lane(32)]
    if (i >= 128) return;
    int lane = i & 31;
    int s = (i >> 5) & 1;
    int mtile = i >> 6;
    int gID = lane >> 2, qID = lane & 3;
    uint32_t h[4], l[4];
#pragma unroll
    for (int e = 0; e < 4; e++) {
        int m = mtile * 16 + gID + 8 * (e & 1);
        int kp = qID + 4 * (e >> 1);
        int k0 = s * 16 + 2 * kp, k1 = k0 + 1;
        float w0 = (k0 < 27) ? wgt[(m * 3 + k0 / 9) * 9 + (k0 % 9)] : 0.f;
        float w1 = (k1 < 27) ? wgt[(m * 3 + k1 / 9) * 9 + (k1 % 9)] : 0.f;
        uint2 sp = split_bf16_pair(w0, w1);
        h[e] = sp.x; l[e] = sp.y;
    }
    WH[i] = make_uint4(h[0], h[1], h[2], h[3]);
    WL[i] = make_uint4(l[0], l[1], l[2], l[3]);
}

// ---------------- conv1: half-image tiles, 256 thr, bf16 TC + BN + ReLU + maxpool -----
// Block handles 16 output rows of one image. GEMM: M=32, K=32 (2 steps), N=512 px.
__global__ __launch_bounds__(256) void conv1_tc(
    const uint4* __restrict__ WH, const uint4* __restrict__ WL,
    const float* __restrict__ in,
    const float* __restrict__ bias, const float* __restrict__ gamma,
    const float* __restrict__ beta, float* __restrict__ out)
{
    extern __shared__ unsigned char sm1[];
    float* raw = (float*)sm1;                        // [3][18][34] = 1836 floats
    uint2* Bt = (uint2*)(sm1 + 7424);                // [16][516]

    const int t = threadIdx.x;
    const int warp = t >> 5, lane = t & 31;
    const int gID = lane >> 2, qID = lane & 3;
    const int b = blockIdx.x;
    const int y_base = blockIdx.y * 16;
    const int nwbase = warp * 64;

    // phase 1: raw padded tile (18 rows = 16 + halo)
    for (int i = t; i < 3 * 18 * 34; i += 256) {
        int ci = i / 612, p = i % 612;
        int y = y_base + p / 34 - 1, x = p % 34 - 1;
        float v = 0.f;
        if ((unsigned)y < 32u && (unsigned)x < 32u)
            v = in[((long)b * 3 + ci) * 1024 + y * 32 + x];
        raw[i] = v;
    }
    __syncthreads();

    // phase 2: build im2col pair tile (thread t: pair row j = t>>4, lanes xh = t&15)
    {
        int j = t >> 4;
        int xh = t & 15;
        int k0 = 2 * j, k1 = 2 * j + 1;
        bool z0 = k0 >= 27, z1 = k1 >= 27;
        int off0 = z0 ? 0 : (k0 / 9) * 612 + ((k0 % 9) / 3) * 34 + (k0 % 9) % 3;
        int off1 = z1 ? 0 : (k1 / 9) * 612 + ((k1 % 9) / 3) * 34 + (k1 % 9) % 3;
#pragma unroll 4
        for (int y = 0; y < 16; y++) {
#pragma unroll
            for (int xs = 0; xs < 2; xs++) {
                int x = xh + xs * 16;
                int rb = y * 34 + x;
                float v0 = z0 ? 0.f : raw[off0 + rb];
                float v1 = z1 ? 0.f : raw[off1 + rb];
                Bt[j * 516 + y * 32 + x] = split_bf16_pair(v0, v1);
            }
        }
    }
    __syncthreads();

    float acc[2][8][4];
#pragma unroll
    for (int mf = 0; mf < 2; mf++)
#pragma unroll
        for (int nf = 0; nf < 8; nf++)
#pragma unroll
            for (int e = 0; e < 4; e++) acc[mf][nf][e] = 0.f;

    int npx[8];
#pragma unroll
    for (int nf = 0; nf < 8; nf++) npx[nf] = nwbase + nf * 8 + gID;

#pragma unroll
    for (int s = 0; s < 2; s++) {
        uint32_t ah[2][4], al[2][4];
#pragma unroll
        for (int mf = 0; mf < 2; mf++) {
            uint4 h = WH[(mf * 2 + s) * 32 + lane];
            uint4 l = WL[(mf * 2 + s) * 32 + lane];
            ah[mf][0] = h.x; ah[mf][1] = h.y; ah[mf][2] = h.z; ah[mf][3] = h.w;
            al[mf][0] = l.x; al[mf][1] = l.y; al[mf][2] = l.z; al[mf][3] = l.w;
        }
#pragma unroll
        for (int nf = 0; nf < 8; nf++) {
            uint2 u1 = Bt[(s * 8 + qID) * 516 + npx[nf]];
            uint2 u2 = Bt[(s * 8 + qID + 4) * 516 + npx[nf]];
            uint32_t bh[2] = {u1.x, u2.x};
            uint32_t bl[2] = {u1.y, u2.y};
#pragma unroll
            for (int mf = 0; mf < 2; mf++) {
                MMA_BF16(acc[mf][nf], ah[mf], bh);
                MMA_BF16(acc[mf][nf], ah[mf], bl);
                MMA_BF16(acc[mf][nf], al[mf], bh);
            }
        }
    }

    // epilogue: BN + ReLU + 2x2 maxpool; nf pairs with nf+4 (vertical partner)
#pragma unroll
    for (int nf = 0; nf < 4; nf++) {
        int pf = nf + 4;
        int n0 = nwbase + nf * 8 + 2 * qID;
        int py = blockIdx.y * 8 + ((n0 >> 5) >> 1);
        int pxo = (n0 & 31) >> 1;
#pragma unroll
        for (int mf = 0; mf < 2; mf++)
#pragma unroll
            for (int half = 0; half < 2; half++) {
                int m = mf * 16 + gID + half * 8;
                float sc = gamma[m] * INVBN;
                float bi = bias[m], bt = beta[m];
                float v00 = fmaxf(sc * (acc[mf][nf][2 * half + 0] + bi) + bt, 0.f);
                float v01 = fmaxf(sc * (acc[mf][nf][2 * half + 1] + bi) + bt, 0.f);
                float v10 = fmaxf(sc * (acc[mf][pf][2 * half + 0] + bi) + bt, 0.f);
                float v11 = fmaxf(sc * (acc[mf][pf][2 * half + 1] + bi) + bt, 0.f);
                float pv = fmaxf(fmaxf(v00, v01), fmaxf(v10, v11));
                out[((long)b * 32 + m) * 256 + py * 16 + pxo] = pv;
            }
    }
}

// ---------------- bf16-split tensor-core conv3x3 + BN + ReLU + fused 2x2 pool ----------
template<int CIN, int COUT, int H, int W, int IMGS, int WARPS_M, int WARPS_N, int POOL>
__global__ __launch_bounds__(WARPS_M * WARPS_N * 32) void conv_tc_pool(
    const uint4* __restrict__ WH, const uint4* __restrict__ WL,
    const float* __restrict__ in,
    const float* __restrict__ bias, const float* __restrict__ gamma,
    const float* __restrict__ beta, float* __restrict__ out)
{
    constexpr int NTHR = WARPS_M * WARPS_N * 32;
    constexpr int NC = CIN / 16;
    constexpr int S_TOT = NC * 9;
    constexpr int TH = H + 2, TW = W + 2;
    constexpr int THW = TH * TW;
    constexpr int PELEMS = IMGS * 8 * THW;
    constexpr int NSTG = (PELEMS + NTHR - 1) / NTHR;
    constexpr int HW = H * W;
    constexpr int NFH = W / 8;
    static_assert(WARPS_M * 32 == COUT, "M partition");
    static_assert(WARPS_N * 64 == IMGS * HW, "N partition");

    extern __shared__ unsigned char cvsm[];
    uint2* tile2 = (uint2*)cvsm;               // [2][PELEMS]

    const int t = threadIdx.x;
    const int warp = t >> 5, lane = t & 31;
    const int gID = lane >> 2, qID = lane & 3;
    const int mtile0 = (warp % WARPS_M) * 2;
    const int nwbase = (warp / WARPS_M) * 64;
    const int b0 = blockIdx.x * IMGS;
    const int qoff1 = qID * THW;
    const int qoff2 = (qID + 4) * THW;

    int nbase[8];
#pragma unroll
    for (int nf = 0; nf < 8; nf++) {
        int n = nwbase + nf * 8 + gID;
        int img = n / HW, rem = n % HW;
        nbase[nf] = img * 8 * THW + (rem / W) * TW + (rem % W);
    }

    float acc[2][8][4];
#pragma unroll
    for (int mf = 0; mf < 2; mf++)
#pragma unroll
        for (int nf = 0; nf < 8; nf++)
#pragma unroll
            for (int e = 0; e < 4; e++) acc[mf][nf][e] = 0.f;

    float2 sreg[NSTG];
    auto stage_load = [&](int cc) {
#pragma unroll
        for (int j = 0; j < NSTG; j++) {
            int i = t + j * NTHR;
            float v0 = 0.f, v1 = 0.f;
            if (i < PELEMS) {
                int img = i / (8 * THW);
                int r2 = i % (8 * THW);
                int cp = r2 / THW;
                int p = r2 % THW;
                int y = p / TW - 1, x = p % TW - 1;
                if ((unsigned)y < (unsigned)H && (unsigned)x < (unsigned)W) {
                    const float* base = in + (((long)(b0 + img) * CIN + cc * 16 + 2 * cp) * H + y) * W + x;
                    v0 = base[0];
                    v1 = base[H * W];
                }
            }
            sreg[j] = make_float2(v0, v1);
        }
    };
    auto stage_store = [&](int buf) {
#pragma unroll
        for (int j = 0; j < NSTG; j++) {
            int i = t + j * NTHR;
            if (i < PELEMS) tile2[buf * PELEMS + i] = split_bf16_pair(sreg[j].x, sreg[j].y);
        }
    };

    stage_load(0);
    stage_store(0);
    __syncthreads();

    int buf = 0;
#pragma unroll 1
    for (int cc = 0; cc < NC; cc++) {
        if (cc + 1 < NC) stage_load(cc + 1);
        const uint2* tb = tile2 + buf * PELEMS;
#pragma unroll 1
        for (int s = 0; s < 9; s++) {
            int off = (s / 3) * TW + (s % 3);
            uint32_t ah[2][4], al[2][4];
#pragma unroll
            for (int mf = 0; mf < 2; mf++) {
                long fi = ((long)(mtile0 + mf) * S_TOT + cc * 9 + s) * 32 + lane;
                uint4 h = WH[fi]; uint4 l = WL[fi];
                ah[mf][0] = h.x; ah[mf][1] = h.y; ah[mf][2] = h.z; ah[mf][3] = h.w;
                al[mf][0] = l.x; al[mf][1] = l.y; al[mf][2] = l.z; al[mf][3] = l.w;
            }
#pragma unroll
            for (int nf = 0; nf < 8; nf++) {
                uint2 u1 = tb[nbase[nf] + qoff1 + off];
                uint2 u2 = tb[nbase[nf] + qoff2 + off];
                uint32_t bh[2] = {u1.x, u2.x};
                uint32_t bl[2] = {u1.y, u2.y};
#pragma unroll
                for (int mf = 0; mf < 2; mf++) {
                    MMA_BF16(acc[mf][nf], ah[mf], bh);
                    MMA_BF16(acc[mf][nf], ah[mf], bl);
                    MMA_BF16(acc[mf][nf], al[mf], bh);
                }
            }
        }
        if (cc + 1 < NC) stage_store(buf ^ 1);
        __syncthreads();
        buf ^= 1;
    }

#pragma unroll
    for (int nf = 0; nf < 8; nf++) {
        if (((nf / NFH) & 1) != 0) continue;
        int pf = nf + NFH;
        int n0 = nwbase + nf * 8 + 2 * qID;
        int img = n0 / HW, rem = n0 % HW;
        int py = (rem / W) / 2, px = (rem % W) / 2;
#pragma unroll
        for (int mf = 0; mf < 2; mf++)
#pragma unroll
            for (int half = 0; half < 2; half++) {
                int m = (mtile0 + mf) * 16 + gID + half * 8;
                float sc = gamma[m] * INVBN;
                float bi = bias[m], bt = beta[m];
                float v00 = fmaxf(sc * (acc[mf][nf][2 * half + 0] + bi) + bt, 0.f);
                float v01 = fmaxf(sc * (acc[mf][nf][2 * half + 1] + bi) + bt, 0.f);
                float v10 = fmaxf(sc * (acc[mf][pf][2 * half + 0] + bi) + bt, 0.f);
                float v11 = fmaxf(sc * (acc[mf][pf][2 * half + 1] + bi) + bt, 0.f);
                float pv;
                if (POOL == 0) pv = fmaxf(fmaxf(v00, v01), fmaxf(v10, v11));
                else pv = 0.25f * ((v00 + v01) + (v10 + v11));
                out[((long)(b0 + img) * COUT + m) * (HW / 4) + py * (W / 2) + px] = pv;
            }
    }
}

// ---------------- fc1 via bf16-split tensor cores ----------------
// C[1024,512] = relu(A[1024,2048] @ W[512,2048]^T + bias). 64x64 tile, BK=32,
// cp.async staging to float smem, per-tile convert to pair smem, k16 MMAs.
__device__ __forceinline__ void cp_async16(uint32_t s, const void* g) {
    asm volatile("cp.async.cg.shared.global [%0], [%1], 16;" :: "r"(s), "l"(g));
}

__global__ __launch_bounds__(128) void fc1_tc_kernel(
    const float* __restrict__ A, const float* __restrict__ Wt,
    const float* __restrict__ bias, float* __restrict__ C)
{
    __shared__ float As[64][36];
    __shared__ float Bs[64][36];
    __shared__ uint2 Ap[64][20];
    __shared__ uint2 Bp[64][20];

    const int t = threadIdx.x;
    const int wid = t >> 5, lane = t & 31;
    const int gID = lane >> 2, qID = lane & 3;
    const int wm = (wid & 1) * 32, wn = (wid >> 1) * 32;
    const int rowT = blockIdx.y * 64;
    const int colT = blockIdx.x * 64;

    const uint32_t asb = (uint32_t)__cvta_generic_to_shared(&As[0][0]);
    const uint32_t bsb = (uint32_t)__cvta_generic_to_shared(&Bs[0][0]);

    float acc[2][4][4];
#pragma unroll
    for (int i = 0; i < 2; i++)
#pragma unroll
        for (int j = 0; j < 4; j++)
#pragma unroll
            for (int e = 0; e < 4; e++) acc[i][j][e] = 0.f;

    auto load_tile = [&](int k0) {
#pragma unroll
        for (int i = 0; i < 4; i++) {
            int idx = t + i * 128;
            int row = idx >> 3, kq = idx & 7;
            uint32_t soff = (uint32_t)((row * 36 + kq * 4) * 4);
            cp_async16(asb + soff, A + (long)(rowT + row) * 2048 + k0 + kq * 4);
            cp_async16(bsb + soff, Wt + (long)(colT + row) * 2048 + k0 + kq * 4);
        }
        asm volatile("cp.async.commit_group;");
    };

    load_tile(0);
    for (int kt = 0; kt < 64; kt++) {
        asm volatile("cp.async.wait_group 0;" ::: "memory");
        __syncthreads();
        // convert float tiles -> pair tiles (8 pairs per thread per matrix)
#pragma unroll
        for (int j = 0; j < 8; j++) {
            int pi = t + j * 128;
            int row = pi >> 4, pr = pi & 15;
            float a0 = As[row][2 * pr], a1 = As[row][2 * pr + 1];
            Ap[row][pr] = split_bf16_pair(a0, a1);
            float b0 = Bs[row][2 * pr], b1 = Bs[row][2 * pr + 1];
            Bp[row][pr] = split_bf16_pair(b0, b1);
        }
        __syncthreads();
        if (kt < 63) load_tile((kt + 1) * 32);   // safe: floats consumed

#pragma unroll
        for (int kk = 0; kk < 2; kk++) {
            int p0 = kk * 8 + qID, p1 = p0 + 4;
            uint32_t ah[2][4], al[2][4];
#pragma unroll
            for (int mf = 0; mf < 2; mf++) {
                int r0 = wm + mf * 16 + gID, r1 = r0 + 8;
                uint2 x00 = Ap[r0][p0], x10 = Ap[r1][p0];
                uint2 x01 = Ap[r0][p1], x11 = Ap[r1][p1];
                ah[mf][0] = x00.x; ah[mf][1] = x10.x; ah[mf][2] = x01.x; ah[mf][3] = x11.x;
                al[mf][0] = x00.y; al[mf][1] = x10.y; al[mf][2] = x01.y; al[mf][3] = x11.y;
            }
#pragma unroll
            for (int nf = 0; nf < 4; nf++) {
                int cn = wn + nf * 8 + gID;
                uint2 y0 = Bp[cn][p0], y1 = Bp[cn][p1];
                uint32_t bh[2] = {y0.x, y1.x};
                uint32_t bl[2] = {y0.y, y1.y};
#pragma unroll
                for (int mf = 0; mf < 2; mf++) {
                    MMA_BF16(acc[mf][nf], ah[mf], bh);
                    MMA_BF16(acc[mf][nf], ah[mf], bl);
                    MMA_BF16(acc[mf][nf], al[mf], bh);
                }
            }
        }
    }

#pragma unroll
    for (int mf = 0; mf < 2; mf++)
#pragma unroll
        for (int nf = 0; nf < 4; nf++) {
            int m0 = rowT + wm + mf * 16 + gID;
            int n0 = colT + wn + nf * 8 + 2 * qID;
            float bb0 = bias[n0], bb1 = bias[n0 + 1];
            float2 v0, v1;
            v0.x = fmaxf(acc[mf][nf][0] + bb0, 0.f);
            v0.y = fmaxf(acc[mf][nf][1] + bb1, 0.f);
            v1.x = fmaxf(acc[mf][nf][2] + bb0, 0.f);
            v1.y = fmaxf(acc[mf][nf][3] + bb1, 0.f);
            *(float2*)&C[(long)m0 * 512 + n0] = v0;
            *(float2*)&C[(long)(m0 + 8) * 512 + n0] = v1;
        }
}

// ---------------- fused tail: fc2 + softmax + quantum layer + head ----------------
__global__ __launch_bounds__(256) void tail_kernel(
    const float* __restrict__ H, const float* __restrict__ W2,
    const float* __restrict__ b2, const float* __restrict__ qw,
    const float* __restrict__ h1w, const float* __restrict__ h1b,
    const float* __restrict__ bng, const float* __restrict__ bnb,
    const float* __restrict__ h2w, const float* __restrict__ h2b,
    float* __restrict__ out)
{
    __shared__ float U1re[256], U1im[256], U2re[256], U2im[256];
    __shared__ float Mre_s[256], Mim_s[256];
    __shared__ float ysm[8][128];
    int t = threadIdx.x;
    {
        int r = t >> 4, c = t & 15;
        for (int l = 0; l < 2; l++) {
            float cq[4], sq[4];
#pragma unroll
            for (int q = 0; q < 4; q++) {
                float th = qw[l * 4 + q] * 0.5f;
                cq[q] = cosf(th);
                sq[q] = sinf(th);
            }
            float re = 1.f, im = 0.f;
#pragma unroll
            for (int q = 0; q < 4; q++) {
                int br = (r >> (3 - q)) & 1;
                int bc = (c >> (3 - q)) & 1;
                if (br == bc) { re *= cq[q]; im *= cq[q]; }
                else { float nr = sq[q] * im; float ni = -sq[q] * re; re = nr; im = ni; }
            }
            int bb = r;
            if ((bb >> 3) & 1) bb ^= 4;
            if ((bb >> 2) & 1) bb ^= 2;
            if ((bb >> 1) & 1) bb ^= 1;
            if (bb & 1)        bb ^= 8;
            if (l == 0) { U1re[bb * 16 + c] = re; U1im[bb * 16 + c] = im; }
            else        { U2re[bb * 16 + c] = re; U2im[bb * 16 + c] = im; }
        }
        __syncthreads();
        float mre = 0.f, mim = 0.f;
#pragma unroll
        for (int k = 0; k < 16; k++) {
            float are = U2re[r * 16 + k], aim = U2im[r * 16 + k];
            float bre = U1re[k * 16 + c], bim = U1im[k * 16 + c];
            mre += are * bre - aim * bim;
            mim += are * bim + aim * bre;
        }
        Mre_s[t] = mre;
        Mim_s[t] = mim;
    }
    __syncthreads();

    int warp = t >> 5, lane = t & 31;
    int b = blockIdx.x * 8 + warp;
    int j = lane & 15;

    // fc2: logits
    float logit = 0.f;
    if (lane < 16) {
        const float* hr = H + b * 512;
        const float* wr = W2 + lane * 512;
        float a0 = 0.f, a1 = 0.f, a2 = 0.f, a3 = 0.f;
        for (int k = 0; k < 512; k += 4) {
            a0 = fmaf(hr[k + 0], wr[k + 0], a0);
            a1 = fmaf(hr[k + 1], wr[k + 1], a1);
            a2 = fmaf(hr[k + 2], wr[k + 2], a2);
            a3 = fmaf(hr[k + 3], wr[k + 3], a3);
        }
        logit = (a0 + a1) + (a2 + a3) + b2[lane];
    }
    float mx = warp_max(lane < 16 ? logit : -3.0e38f);
    float e = (lane < 16) ? expf(logit - mx) : 0.f;
    float sum = warp_sum(e);
    float f = (lane < 16) ? e / sum : 0.f;

    // quantum: normalize, psi = M p, probs, Z expvals
    float n2 = warp_sum(f * f);
    float p0 = f / sqrtf(n2);

    float pre = 0.f, pim = 0.f;
#pragma unroll
    for (int k = 0; k < 16; k++) {
        float pk = __shfl_sync(0xffffffffu, p0, k);
        pre = fmaf(Mre_s[j * 16 + k], pk, pre);
        pim = fmaf(Mim_s[j * 16 + k], pk, pim);
    }
    float prob = (lane < 16) ? (pre * pre + pim * pim) : 0.f;

    float qv[4];
#pragma unroll
    for (int w = 0; w < 4; w++) {
        float sgn = 1.f - 2.f * (float)((j >> (3 - w)) & 1);
        qv[w] = warp_sum(prob * sgn);
    }

    // head: 4 -> 128, BN + ReLU
#pragma unroll
    for (int i = 0; i < 4; i++) {
        int n = lane + i * 32;
        float v = qv[0] * h1w[n * 4 + 0] + qv[1] * h1w[n * 4 + 1]
                + qv[2] * h1w[n * 4 + 2] + qv[3] * h1w[n * 4 + 3] + h1b[n];
        v = bng[n] * v * INVBN + bnb[n];
        ysm[warp][n] = fmaxf(v, 0.f);
    }
    __syncwarp();

    // 128 -> 100
#pragma unroll
    for (int i = 0; i < 4; i++) {
        int m = lane + i * 32;
        if (m < 100) {
            float s = h2b[m];
            const float* hw = h2w + m * 128;
#pragma unroll 8
            for (int n = 0; n < 128; n++) s = fmaf(ysm[warp][n], hw[n], s);
            out[b * 100 + m] = s;
        }
    }
}

// ---------------- launch ----------------
extern "C" void kernel_launch(void* const* d_in, const int* in_sizes, int n_in,
                              void* d_out, int out_size)
{
    (void)in_sizes; (void)n_in; (void)out_size;
    const float* x    = (const float*)d_in[0];
    const float* c1w  = (const float*)d_in[1];
    const float* c1b  = (const float*)d_in[2];
    const float* g1   = (const float*)d_in[3];
    const float* be1  = (const float*)d_in[4];
    const float* c2w  = (const float*)d_in[5];
    const float* c2b  = (const float*)d_in[6];
    const float* g2   = (const float*)d_in[7];
    const float* be2  = (const float*)d_in[8];
    const float* c3w  = (const float*)d_in[9];
    const float* c3b  = (const float*)d_in[10];
    const float* g3   = (const float*)d_in[11];
    const float* be3  = (const float*)d_in[12];
    const float* fr1w = (const float*)d_in[13];
    const float* fr1b = (const float*)d_in[14];
    const float* fr2w = (const float*)d_in[15];
    const float* fr2b = (const float*)d_in[16];
    const float* qw   = (const float*)d_in[17];
    const float* h1w  = (const float*)d_in[18];
    const float* h1b  = (const float*)d_in[19];
    const float* bng  = (const float*)d_in[20];
    const float* bnb  = (const float*)d_in[21];
    const float* h2w  = (const float*)d_in[22];
    const float* h2b  = (const float*)d_in[23];
    float* out = (float*)d_out;

    float *p1, *p2, *flat, *fc1o;
    uint4 *wf1h, *wf1l, *wf2h, *wf2l, *wf3h, *wf3l;
    cudaGetSymbolAddress((void**)&p1, g_p1);
    cudaGetSymbolAddress((void**)&p2, g_p2);
    cudaGetSymbolAddress((void**)&flat, g_flat);
    cudaGetSymbolAddress((void**)&fc1o, g_fc1);
    cudaGetSymbolAddress((void**)&wf1h, g_wf1h);
    cudaGetSymbolAddress((void**)&wf1l, g_wf1l);
    cudaGetSymbolAddress((void**)&wf2h, g_wf2h);
    cudaGetSymbolAddress((void**)&wf2l, g_wf2l);
    cudaGetSymbolAddress((void**)&wf3h, g_wf3h);
    cudaGetSymbolAddress((void**)&wf3l, g_wf3l);

    constexpr int SM1 = 7424 + 16 * 516 * 8;          // conv1: ~71.8 KB
    constexpr int SM2 = 2 * (1 * 8 * 18 * 18) * 8;    // conv2: ~41.5 KB
    constexpr int SM3 = 2 * (2 * 8 * 10 * 10) * 8;    // conv3: ~25.6 KB
    cudaFuncSetAttribute(conv1_tc, cudaFuncAttributeMaxDynamicSharedMemorySize, SM1);
    cudaFuncSetAttribute(conv_tc_pool<32, 64, 16, 16, 1, 2, 4, 0>,
                         cudaFuncAttributeMaxDynamicSharedMemorySize, SM2);
    cudaFuncSetAttribute(conv_tc_pool<64, 128, 8, 8, 2, 4, 2, 1>,
                         cudaFuncAttributeMaxDynamicSharedMemorySize, SM3);

    // weight pre-split into bf16 fragment order
    wsplit_conv1<<<1, 128>>>(c1w, wf1h, wf1l);
    wsplit_frag_kernel<32, 64><<<(4 * 18 * 32 + 255) / 256, 256>>>(c2w, wf2h, wf2l);
    wsplit_frag_kernel<64, 128><<<(8 * 36 * 32 + 255) / 256, 256>>>(c3w, wf3h, wf3l);

    // conv1 (3->32, 32x32) + maxpool -> [B,32,16,16]  (bf16 TC, half-image tiles)
    conv1_tc<<<dim3(1024, 2), 256, SM1>>>(wf1h, wf1l, x, c1b, g1, be1, p1);
    // conv2 (32->64, 16x16) + maxpool -> [B,64,8,8]
    conv_tc_pool<32, 64, 16, 16, 1, 2, 4, 0><<<1024, 256, SM2>>>(wf2h, wf2l, p1, c2b, g2, be2, p2);
    // conv3 (64->128, 8x8) + avgpool -> flatten [B,2048]
    conv_tc_pool<64, 128, 8, 8, 2, 4, 2, 1><<<512, 256, SM3>>>(wf3h, wf3l, p2, c3b, g3, be3, flat);

    fc1_tc_kernel<<<dim3(8, 16), 128>>>(flat, fr1w, fr1b, fc1o);
    tail_kernel<<<128, 256>>>(fc1o, fr2w, fr2b, qw, h1w, h1b, bng, bnb, h2w, h2b, out);
}

// round 17
// speedup vs baseline: 1.0542x; 1.0542x over previous
#include <cuda_runtime.h>
#include <cuda_bf16.h>
#include <math.h>
#include <stdint.h>

#define BATCH 1024

// ---------------- scratch (static device globals; no allocs allowed) ----------------
__device__ float g_p1[BATCH*32*16*16];   // conv1+maxpool out
__device__ float g_p2[BATCH*64*8*8];     // conv2+maxpool out
__device__ float g_flat[BATCH*2048];     // conv3+avgpool out (flatten)
__device__ float g_fc1[BATCH*512];       // fc1 out
// fragment-ordered conv weights (bf16x2 hi/lo, SoA)
__device__ uint4 g_wf1h[2*2*32];
__device__ uint4 g_wf1l[2*2*32];
__device__ uint4 g_wf2h[4*18*32];
__device__ uint4 g_wf2l[4*18*32];
__device__ uint4 g_wf3h[8*36*32];
__device__ uint4 g_wf3l[8*36*32];

static const float INVBN = 0.9999950000374998f; // 1/sqrt(1+1e-5)

__device__ __forceinline__ float warp_sum(float v) {
#pragma unroll
    for (int o = 16; o > 0; o >>= 1) v += __shfl_xor_sync(0xffffffffu, v, o);
    return v;
}
__device__ __forceinline__ float warp_max(float v) {
#pragma unroll
    for (int o = 16; o > 0; o >>= 1) v = fmaxf(v, __shfl_xor_sync(0xffffffffu, v, o));
    return v;
}

__device__ __forceinline__ uint32_t f2tf32(float x) {
    uint32_t h; asm("cvt.rna.tf32.f32 %0, %1;" : "=r"(h) : "f"(x)); return h;
}
// pack two floats to bf16x2: low half = lo, high half = hi
__device__ __forceinline__ uint32_t pk_bf16x2(float lo, float hi) {
    uint32_t r; asm("cvt.rn.bf16x2.f32 %0, %1, %2;" : "=r"(r) : "f"(hi), "f"(lo)); return r;
}
__device__ __forceinline__ uint2 split_bf16_pair(float v0, float v1) {
    uint32_t h = pk_bf16x2(v0, v1);
    float h0 = __uint_as_float(h << 16);
    float h1 = __uint_as_float(h & 0xffff0000u);
    uint32_t l = pk_bf16x2(v0 - h0, v1 - h1);
    return make_uint2(h, l);
}

#define MMA_TF32(Cv, Aa, Bb) \
    asm volatile("mma.sync.aligned.m16n8k8.row.col.f32.tf32.tf32.f32 " \
                 "{%0,%1,%2,%3},{%4,%5,%6,%7},{%8,%9},{%0,%1,%2,%3};" \
                 : "+f"((Cv)[0]), "+f"((Cv)[1]), "+f"((Cv)[2]), "+f"((Cv)[3]) \
                 : "r"((Aa)[0]), "r"((Aa)[1]), "r"((Aa)[2]), "r"((Aa)[3]), \
                   "r"((Bb)[0]), "r"((Bb)[1]))

#define MMA_BF16(Cv, Aa, Bb) \
    asm volatile("mma.sync.aligned.m16n8k16.row.col.f32.bf16.bf16.f32 " \
                 "{%0,%1,%2,%3},{%4,%5,%6,%7},{%8,%9},{%0,%1,%2,%3};" \
                 : "+f"((Cv)[0]), "+f"((Cv)[1]), "+f"((Cv)[2]), "+f"((Cv)[3]) \
                 : "r"((Aa)[0]), "r"((Aa)[1]), "r"((Aa)[2]), "r"((Aa)[3]), \
                   "r"((Bb)[0]), "r"((Bb)[1]))

// ---------------- weight pre-split (chunked convs: K = 16 channels per tap) ----------
template<int CIN, int COUT>
__global__ void wsplit_frag_kernel(const float* __restrict__ wgt,
                                   uint4* __restrict__ WH, uint4* __restrict__ WL)
{
    constexpr int S_TOT = (CIN / 16) * 9;
    int i = blockIdx.x * 256 + threadIdx.x;
    if (i >= (COUT / 16) * S_TOT * 32) return;
    int lane = i & 31;
    int g = (i >> 5) % S_TOT;
    int mtile = (i >> 5) / S_TOT;
    int gID = lane >> 2, qID = lane & 3;
    int cc = g / 9, s = g % 9;
    uint32_t h[4], l[4];
#pragma unroll
    for (int e = 0; e < 4; e++) {
        int m = mtile * 16 + gID + 8 * (e & 1);
        int kpair = qID + 4 * (e >> 1);
        int ci0 = cc * 16 + 2 * kpair;
        float w0 = wgt[(m * CIN + ci0) * 9 + s];
        float w1 = wgt[(m * CIN + ci0 + 1) * 9 + s];
        uint2 sp = split_bf16_pair(w0, w1);
        h[e] = sp.x; l[e] = sp.y;
    }
    WH[i] = make_uint4(h[0], h[1], h[2], h[3]);
    WL[i] = make_uint4(l[0], l[1], l[2], l[3]);
}

// ---------------- conv1 weight pre-split: K = ci*9+tap (27, padded to 32) ------------
__global__ void wsplit_conv1(const float* __restrict__ wgt,
                             uint4* __restrict__ WH, uint4* __restrict__ WL)
{
    int i = threadIdx.x;  // 128 threads: [mtile(2)][kstep(2)][lane(32)]
    if (i >= 128) return;
    int lane = i & 31;
    int s = (i >> 5) & 1;
    int mtile = i >> 6;
    int gID = lane >> 2, qID = lane & 3;
    uint32_t h[4], l[4];
#pragma unroll
    for (int e = 0; e < 4; e++) {
        int m = mtile * 16 + gID + 8 * (e & 1);
        int kp = qID + 4 * (e >> 1);
        int k0 = s * 16 + 2 * kp, k1 = k0 + 1;
        float w0 = (k0 < 27) ? wgt[(m * 3 + k0 / 9) * 9 + (k0 % 9)] : 0.f;
        float w1 = (k1 < 27) ? wgt[(m * 3 + k1 / 9) * 9 + (k1 % 9)] : 0.f;
        uint2 sp = split_bf16_pair(w0, w1);
        h[e] = sp.x; l[e] = sp.y;
    }
    WH[i] = make_uint4(h[0], h[1], h[2], h[3]);
    WL[i] = make_uint4(l[0], l[1], l[2], l[3]);
}

// ---------------- conv1: quarter-image tiles, 256 thr, bf16 TC + BN + ReLU + maxpool --
// Block handles 8 output rows of one image. 8 warps = 2 m-tiles x 4 n-quarters.
// GEMM per warp: 1 m16-tile x 8 n8-tiles, K=32 (2 steps).
__global__ __launch_bounds__(256) void conv1_tc(
    const uint4* __restrict__ WH, const uint4* __restrict__ WL,
    const float* __restrict__ in,
    const float* __restrict__ bias, const float* __restrict__ gamma,
    const float* __restrict__ beta, float* __restrict__ out)
{
    extern __shared__ unsigned char sm1[];
    float* raw = (float*)sm1;                        // [3][10][34] = 1020 floats
    uint2* Bt = (uint2*)(sm1 + 4096);                // [16][260]

    const int t = threadIdx.x;
    const int warp = t >> 5, lane = t & 31;
    const int gID = lane >> 2, qID = lane & 3;
    const int b = blockIdx.x;
    const int y_base = blockIdx.y * 8;
    const int mtile = warp >> 2;
    const int nwbase = (warp & 3) * 64;

    // phase 1: raw padded tile (10 rows = 8 + halo)
    for (int i = t; i < 3 * 10 * 34; i += 256) {
        int ci = i / 340, p = i % 340;
        int y = y_base + p / 34 - 1, x = p % 34 - 1;
        float v = 0.f;
        if ((unsigned)y < 32u && (unsigned)x < 32u)
            v = in[((long)b * 3 + ci) * 1024 + y * 32 + x];
        raw[i] = v;
    }
    __syncthreads();

    // phase 2: build im2col pair tile (thread t: pair row j = t>>4, lanes xh = t&15)
    {
        int j = t >> 4;
        int xh = t & 15;
        int k0 = 2 * j, k1 = 2 * j + 1;
        bool z0 = k0 >= 27, z1 = k1 >= 27;
        int off0 = z0 ? 0 : (k0 / 9) * 340 + ((k0 % 9) / 3) * 34 + (k0 % 9) % 3;
        int off1 = z1 ? 0 : (k1 / 9) * 340 + ((k1 % 9) / 3) * 34 + (k1 % 9) % 3;
#pragma unroll 4
        for (int y = 0; y < 8; y++) {
#pragma unroll
            for (int xs = 0; xs < 2; xs++) {
                int x = xh + xs * 16;
                int rb = y * 34 + x;
                float v0 = z0 ? 0.f : raw[off0 + rb];
                float v1 = z1 ? 0.f : raw[off1 + rb];
                Bt[j * 260 + y * 32 + x] = split_bf16_pair(v0, v1);
            }
        }
    }
    __syncthreads();

    float acc[8][4];
#pragma unroll
    for (int nf = 0; nf < 8; nf++)
#pragma unroll
        for (int e = 0; e < 4; e++) acc[nf][e] = 0.f;

    int npx[8];
#pragma unroll
    for (int nf = 0; nf < 8; nf++) npx[nf] = nwbase + nf * 8 + gID;

#pragma unroll
    for (int s = 0; s < 2; s++) {
        uint32_t ah[4], al[4];
        {
            uint4 h = WH[(mtile * 2 + s) * 32 + lane];
            uint4 l = WL[(mtile * 2 + s) * 32 + lane];
            ah[0] = h.x; ah[1] = h.y; ah[2] = h.z; ah[3] = h.w;
            al[0] = l.x; al[1] = l.y; al[2] = l.z; al[3] = l.w;
        }
#pragma unroll
        for (int nf = 0; nf < 8; nf++) {
            uint2 u1 = Bt[(s * 8 + qID) * 260 + npx[nf]];
            uint2 u2 = Bt[(s * 8 + qID + 4) * 260 + npx[nf]];
            uint32_t bh[2] = {u1.x, u2.x};
            uint32_t bl[2] = {u1.y, u2.y};
            MMA_BF16(acc[nf], ah, bh);
            MMA_BF16(acc[nf], ah, bl);
            MMA_BF16(acc[nf], al, bh);
        }
    }

    // epilogue: BN + ReLU + 2x2 maxpool; nf pairs with nf+4 (vertical partner)
#pragma unroll
    for (int nf = 0; nf < 4; nf++) {
        int pf = nf + 4;
        int n0 = nwbase + nf * 8 + 2 * qID;
        int py = blockIdx.y * 4 + ((n0 >> 5) >> 1);
        int pxo = (n0 & 31) >> 1;
#pragma unroll
        for (int half = 0; half < 2; half++) {
            int m = mtile * 16 + gID + half * 8;
            float sc = gamma[m] * INVBN;
            float bi = bias[m], bt = beta[m];
            float v00 = fmaxf(sc * (acc[nf][2 * half + 0] + bi) + bt, 0.f);
            float v01 = fmaxf(sc * (acc[nf][2 * half + 1] + bi) + bt, 0.f);
            float v10 = fmaxf(sc * (acc[pf][2 * half + 0] + bi) + bt, 0.f);
            float v11 = fmaxf(sc * (acc[pf][2 * half + 1] + bi) + bt, 0.f);
            float pv = fmaxf(fmaxf(v00, v01), fmaxf(v10, v11));
            out[((long)b * 32 + m) * 256 + py * 16 + pxo] = pv;
        }
    }
}

// ---------------- bf16-split tensor-core conv3x3 + BN + ReLU + fused 2x2 pool ----------
template<int CIN, int COUT, int H, int W, int IMGS, int WARPS_M, int WARPS_N, int POOL>
__global__ __launch_bounds__(WARPS_M * WARPS_N * 32) void conv_tc_pool(
    const uint4* __restrict__ WH, const uint4* __restrict__ WL,
    const float* __restrict__ in,
    const float* __restrict__ bias, const float* __restrict__ gamma,
    const float* __restrict__ beta, float* __restrict__ out)
{
    constexpr int NTHR = WARPS_M * WARPS_N * 32;
    constexpr int NC = CIN / 16;
    constexpr int S_TOT = NC * 9;
    constexpr int TH = H + 2, TW = W + 2;
    constexpr int THW = TH * TW;
    constexpr int PELEMS = IMGS * 8 * THW;
    constexpr int NSTG = (PELEMS + NTHR - 1) / NTHR;
    constexpr int HW = H * W;
    constexpr int NFH = W / 8;
    static_assert(WARPS_M * 32 == COUT, "M partition");
    static_assert(WARPS_N * 64 == IMGS * HW, "N partition");

    extern __shared__ unsigned char cvsm[];
    uint2* tile2 = (uint2*)cvsm;               // [2][PELEMS]

    const int t = threadIdx.x;
    const int warp = t >> 5, lane = t & 31;
    const int gID = lane >> 2, qID = lane & 3;
    const int mtile0 = (warp % WARPS_M) * 2;
    const int nwbase = (warp / WARPS_M) * 64;
    const int b0 = blockIdx.x * IMGS;
    const int qoff1 = qID * THW;
    const int qoff2 = (qID + 4) * THW;

    int nbase[8];
#pragma unroll
    for (int nf = 0; nf < 8; nf++) {
        int n = nwbase + nf * 8 + gID;
        int img = n / HW, rem = n % HW;
        nbase[nf] = img * 8 * THW + (rem / W) * TW + (rem % W);
    }

    float acc[2][8][4];
#pragma unroll
    for (int mf = 0; mf < 2; mf++)
#pragma unroll
        for (int nf = 0; nf < 8; nf++)
#pragma unroll
            for (int e = 0; e < 4; e++) acc[mf][nf][e] = 0.f;

    float2 sreg[NSTG];
    auto stage_load = [&](int cc) {
#pragma unroll
        for (int j = 0; j < NSTG; j++) {
            int i = t + j * NTHR;
            float v0 = 0.f, v1 = 0.f;
            if (i < PELEMS) {
                int img = i / (8 * THW);
                int r2 = i % (8 * THW);
                int cp = r2 / THW;
                int p = r2 % THW;
                int y = p / TW - 1, x = p % TW - 1;
                if ((unsigned)y < (unsigned)H && (unsigned)x < (unsigned)W) {
                    const float* base = in + (((long)(b0 + img) * CIN + cc * 16 + 2 * cp) * H + y) * W + x;
                    v0 = base[0];
                    v1 = base[H * W];
                }
            }
            sreg[j] = make_float2(v0, v1);
        }
    };
    auto stage_store = [&](int buf) {
#pragma unroll
        for (int j = 0; j < NSTG; j++) {
            int i = t + j * NTHR;
            if (i < PELEMS) tile2[buf * PELEMS + i] = split_bf16_pair(sreg[j].x, sreg[j].y);
        }
    };

    stage_load(0);
    stage_store(0);
    __syncthreads();

    int buf = 0;
#pragma unroll 1
    for (int cc = 0; cc < NC; cc++) {
        if (cc + 1 < NC) stage_load(cc + 1);
        const uint2* tb = tile2 + buf * PELEMS;
#pragma unroll 1
        for (int s = 0; s < 9; s++) {
            int off = (s / 3) * TW + (s % 3);
            uint32_t ah[2][4], al[2][4];
#pragma unroll
            for (int mf = 0; mf < 2; mf++) {
                long fi = ((long)(mtile0 + mf) * S_TOT + cc * 9 + s) * 32 + lane;
                uint4 h = WH[fi]; uint4 l = WL[fi];
                ah[mf][0] = h.x; ah[mf][1] = h.y; ah[mf][2] = h.z; ah[mf][3] = h.w;
                al[mf][0] = l.x; al[mf][1] = l.y; al[mf][2] = l.z; al[mf][3] = l.w;
            }
#pragma unroll
            for (int nf = 0; nf < 8; nf++) {
                uint2 u1 = tb[nbase[nf] + qoff1 + off];
                uint2 u2 = tb[nbase[nf] + qoff2 + off];
                uint32_t bh[2] = {u1.x, u2.x};
                uint32_t bl[2] = {u1.y, u2.y};
#pragma unroll
                for (int mf = 0; mf < 2; mf++) {
                    MMA_BF16(acc[mf][nf], ah[mf], bh);
                    MMA_BF16(acc[mf][nf], ah[mf], bl);
                    MMA_BF16(acc[mf][nf], al[mf], bh);
                }
            }
        }
        if (cc + 1 < NC) stage_store(buf ^ 1);
        __syncthreads();
        buf ^= 1;
    }

#pragma unroll
    for (int nf = 0; nf < 8; nf++) {
        if (((nf / NFH) & 1) != 0) continue;
        int pf = nf + NFH;
        int n0 = nwbase + nf * 8 + 2 * qID;
        int img = n0 / HW, rem = n0 % HW;
        int py = (rem / W) / 2, px = (rem % W) / 2;
#pragma unroll
        for (int mf = 0; mf < 2; mf++)
#pragma unroll
            for (int half = 0; half < 2; half++) {
                int m = (mtile0 + mf) * 16 + gID + half * 8;
                float sc = gamma[m] * INVBN;
                float bi = bias[m], bt = beta[m];
                float v00 = fmaxf(sc * (acc[mf][nf][2 * half + 0] + bi) + bt, 0.f);
                float v01 = fmaxf(sc * (acc[mf][nf][2 * half + 1] + bi) + bt, 0.f);
                float v10 = fmaxf(sc * (acc[mf][pf][2 * half + 0] + bi) + bt, 0.f);
                float v11 = fmaxf(sc * (acc[mf][pf][2 * half + 1] + bi) + bt, 0.f);
                float pv;
                if (POOL == 0) pv = fmaxf(fmaxf(v00, v01), fmaxf(v10, v11));
                else pv = 0.25f * ((v00 + v01) + (v10 + v11));
                out[((long)(b0 + img) * COUT + m) * (HW / 4) + py * (W / 2) + px] = pv;
            }
    }
}

// ---------------- fc1 via tf32 tensor cores (R14 known-good version) ----------------
__device__ __forceinline__ void cp_async16(uint32_t s, const void* g) {
    asm volatile("cp.async.cg.shared.global [%0], [%1], 16;" :: "r"(s), "l"(g));
}

__global__ __launch_bounds__(128) void fc1_tc_kernel(
    const float* __restrict__ A, const float* __restrict__ Wt,
    const float* __restrict__ bias, float* __restrict__ C)
{
    __shared__ float As[2][64][36];
    __shared__ float Bs[2][64][36];

    const int t = threadIdx.x;
    const int wid = t >> 5, lane = t & 31;
    const int gID = lane >> 2, qID = lane & 3;
    const int wm = (wid & 1) * 32, wn = (wid >> 1) * 32;
    const int rowT = blockIdx.y * 64;
    const int colT = blockIdx.x * 64;

    const uint32_t asb = (uint32_t)__cvta_generic_to_shared(&As[0][0][0]);
    const uint32_t bsb = (uint32_t)__cvta_generic_to_shared(&Bs[0][0][0]);

    float acc[2][4][4];
#pragma unroll
    for (int i = 0; i < 2; i++)
#pragma unroll
        for (int j = 0; j < 4; j++)
#pragma unroll
            for (int e = 0; e < 4; e++) acc[i][j][e] = 0.f;

    auto load_tile = [&](int buf, int k0) {
#pragma unroll
        for (int i = 0; i < 4; i++) {
            int idx = t + i * 128;
            int row = idx >> 3, kq = idx & 7;
            uint32_t soff = (uint32_t)(((buf * 64 + row) * 36 + kq * 4) * 4);
            cp_async16(asb + soff, A + (long)(rowT + row) * 2048 + k0 + kq * 4);
            cp_async16(bsb + soff, Wt + (long)(colT + row) * 2048 + k0 + kq * 4);
        }
        asm volatile("cp.async.commit_group;");
    };

    load_tile(0, 0);
    int buf = 0;
    for (int kt = 0; kt < 64; kt++) {
        asm volatile("cp.async.wait_group 0;" ::: "memory");
        __syncthreads();
        if (kt < 63) load_tile(buf ^ 1, (kt + 1) * 32);

#pragma unroll
        for (int kk = 0; kk < 4; kk++) {
            uint32_t ah[2][4], al[2][4], bh[4][2], bl[4][2];
#pragma unroll
            for (int mf = 0; mf < 2; mf++)
#pragma unroll
                for (int e = 0; e < 4; e++) {
                    int r = wm + mf * 16 + gID + (e & 1) * 8;
                    int c = kk * 8 + qID + (e >> 1) * 4;
                    float v = As[buf][r][c];
                    uint32_t h = f2tf32(v);
                    ah[mf][e] = h;
                    al[mf][e] = f2tf32(v - __uint_as_float(h));
                }
#pragma unroll
            for (int nf = 0; nf < 4; nf++)
#pragma unroll
                for (int e = 0; e < 2; e++) {
                    int n = wn + nf * 8 + gID;
                    int c = kk * 8 + qID + e * 4;
                    float v = Bs[buf][n][c];
                    uint32_t h = f2tf32(v);
                    bh[nf][e] = h;
                    bl[nf][e] = f2tf32(v - __uint_as_float(h));
                }
#pragma unroll
            for (int mf = 0; mf < 2; mf++)
#pragma unroll
                for (int nf = 0; nf < 4; nf++) {
                    MMA_TF32(acc[mf][nf], ah[mf], bh[nf]);
                    MMA_TF32(acc[mf][nf], ah[mf], bl[nf]);
                    MMA_TF32(acc[mf][nf], al[mf], bh[nf]);
                }
        }
        buf ^= 1;
    }

#pragma unroll
    for (int mf = 0; mf < 2; mf++)
#pragma unroll
        for (int nf = 0; nf < 4; nf++) {
            int m0 = rowT + wm + mf * 16 + gID;
            int n0 = colT + wn + nf * 8 + 2 * qID;
            float bb0 = bias[n0], bb1 = bias[n0 + 1];
            float2 v0, v1;
            v0.x = fmaxf(acc[mf][nf][0] + bb0, 0.f);
            v0.y = fmaxf(acc[mf][nf][1] + bb1, 0.f);
            v1.x = fmaxf(acc[mf][nf][2] + bb0, 0.f);
            v1.y = fmaxf(acc[mf][nf][3] + bb1, 0.f);
            *(float2*)&C[(long)m0 * 512 + n0] = v0;
            *(float2*)&C[(long)(m0 + 8) * 512 + n0] = v1;
        }
}

// ---------------- fused tail: fc2 + softmax + quantum layer + head ----------------
__global__ __launch_bounds__(256) void tail_kernel(
    const float* __restrict__ H, const float* __restrict__ W2,
    const float* __restrict__ b2, const float* __restrict__ qw,
    const float* __restrict__ h1w, const float* __restrict__ h1b,
    const float* __restrict__ bng, const float* __restrict__ bnb,
    const float* __restrict__ h2w, const float* __restrict__ h2b,
    float* __restrict__ out)
{
    __shared__ float U1re[256], U1im[256], U2re[256], U2im[256];
    __shared__ float Mre_s[256], Mim_s[256];
    __shared__ float ysm[8][128];
    int t = threadIdx.x;
    {
        int r = t >> 4, c = t & 15;
        for (int l = 0; l < 2; l++) {
            float cq[4], sq[4];
#pragma unroll
            for (int q = 0; q < 4; q++) {
                float th = qw[l * 4 + q] * 0.5f;
                cq[q] = cosf(th);
                sq[q] = sinf(th);
            }
            float re = 1.f, im = 0.f;
#pragma unroll
            for (int q = 0; q < 4; q++) {
                int br = (r >> (3 - q)) & 1;
                int bc = (c >> (3 - q)) & 1;
                if (br == bc) { re *= cq[q]; im *= cq[q]; }
                else { float nr = sq[q] * im; float ni = -sq[q] * re; re = nr; im = ni; }
            }
            int bb = r;
            if ((bb >> 3) & 1) bb ^= 4;
            if ((bb >> 2) & 1) bb ^= 2;
            if ((bb >> 1) & 1) bb ^= 1;
            if (bb & 1)        bb ^= 8;
            if (l == 0) { U1re[bb * 16 + c] = re; U1im[bb * 16 + c] = im; }
            else        { U2re[bb * 16 + c] = re; U2im[bb * 16 + c] = im; }
        }
        __syncthreads();
        float mre = 0.f, mim = 0.f;
#pragma unroll
        for (int k = 0; k < 16; k++) {
            float are = U2re[r * 16 + k], aim = U2im[r * 16 + k];
            float bre = U1re[k * 16 + c], bim = U1im[k * 16 + c];
            mre += are * bre - aim * bim;
            mim += are * bim + aim * bre;
        }
        Mre_s[t] = mre;
        Mim_s[t] = mim;
    }
    __syncthreads();

    int warp = t >> 5, lane = t & 31;
    int b = blockIdx.x * 8 + warp;
    int j = lane & 15;

    // fc2: logits
    float logit = 0.f;
    if (lane < 16) {
        const float* hr = H + b * 512;
        const float* wr = W2 + lane * 512;
        float a0 = 0.f, a1 = 0.f, a2 = 0.f, a3 = 0.f;
        for (int k = 0; k < 512; k += 4) {
            a0 = fmaf(hr[k + 0], wr[k + 0], a0);
            a1 = fmaf(hr[k + 1], wr[k + 1], a1);
            a2 = fmaf(hr[k + 2], wr[k + 2], a2);
            a3 = fmaf(hr[k + 3], wr[k + 3], a3);
        }
        logit = (a0 + a1) + (a2 + a3) + b2[lane];
    }
    float mx = warp_max(lane < 16 ? logit : -3.0e38f);
    float e = (lane < 16) ? expf(logit - mx) : 0.f;
    float sum = warp_sum(e);
    float f = (lane < 16) ? e / sum : 0.f;

    // quantum: normalize, psi = M p, probs, Z expvals
    float n2 = warp_sum(f * f);
    float p0 = f / sqrtf(n2);

    float pre = 0.f, pim = 0.f;
#pragma unroll
    for (int k = 0; k < 16; k++) {
        float pk = __shfl_sync(0xffffffffu, p0, k);
        pre = fmaf(Mre_s[j * 16 + k], pk, pre);
        pim = fmaf(Mim_s[j * 16 + k], pk, pim);
    }
    float prob = (lane < 16) ? (pre * pre + pim * pim) : 0.f;

    float qv[4];
#pragma unroll
    for (int w = 0; w < 4; w++) {
        float sgn = 1.f - 2.f * (float)((j >> (3 - w)) & 1);
        qv[w] = warp_sum(prob * sgn);
    }

    // head: 4 -> 128, BN + ReLU
#pragma unroll
    for (int i = 0; i < 4; i++) {
        int n = lane + i * 32;
        float v = qv[0] * h1w[n * 4 + 0] + qv[1] * h1w[n * 4 + 1]
                + qv[2] * h1w[n * 4 + 2] + qv[3] * h1w[n * 4 + 3] + h1b[n];
        v = bng[n] * v * INVBN + bnb[n];
        ysm[warp][n] = fmaxf(v, 0.f);
    }
    __syncwarp();

    // 128 -> 100
#pragma unroll
    for (int i = 0; i < 4; i++) {
        int m = lane + i * 32;
        if (m < 100) {
            float s = h2b[m];
            const float* hw = h2w + m * 128;
#pragma unroll 8
            for (int n = 0; n < 128; n++) s = fmaf(ysm[warp][n], hw[n], s);
            out[b * 100 + m] = s;
        }
    }
}

// ---------------- launch ----------------
extern "C" void kernel_launch(void* const* d_in, const int* in_sizes, int n_in,
                              void* d_out, int out_size)
{
    (void)in_sizes; (void)n_in; (void)out_size;
    const float* x    = (const float*)d_in[0];
    const float* c1w  = (const float*)d_in[1];
    const float* c1b  = (const float*)d_in[2];
    const float* g1   = (const float*)d_in[3];
    const float* be1  = (const float*)d_in[4];
    const float* c2w  = (const float*)d_in[5];
    const float* c2b  = (const float*)d_in[6];
    const float* g2   = (const float*)d_in[7];
    const float* be2  = (const float*)d_in[8];
    const float* c3w  = (const float*)d_in[9];
    const float* c3b  = (const float*)d_in[10];
    const float* g3   = (const float*)d_in[11];
    const float* be3  = (const float*)d_in[12];
    const float* fr1w = (const float*)d_in[13];
    const float* fr1b = (const float*)d_in[14];
    const float* fr2w = (const float*)d_in[15];
    const float* fr2b = (const float*)d_in[16];
    const float* qw   = (const float*)d_in[17];
    const float* h1w  = (const float*)d_in[18];
    const float* h1b  = (const float*)d_in[19];
    const float* bng  = (const float*)d_in[20];
    const float* bnb  = (const float*)d_in[21];
    const float* h2w  = (const float*)d_in[22];
    const float* h2b  = (const float*)d_in[23];
    float* out = (float*)d_out;

    float *p1, *p2, *flat, *fc1o;
    uint4 *wf1h, *wf1l, *wf2h, *wf2l, *wf3h, *wf3l;
    cudaGetSymbolAddress((void**)&p1, g_p1);
    cudaGetSymbolAddress((void**)&p2, g_p2);
    cudaGetSymbolAddress((void**)&flat, g_flat);
    cudaGetSymbolAddress((void**)&fc1o, g_fc1);
    cudaGetSymbolAddress((void**)&wf1h, g_wf1h);
    cudaGetSymbolAddress((void**)&wf1l, g_wf1l);
    cudaGetSymbolAddress((void**)&wf2h, g_wf2h);
    cudaGetSymbolAddress((void**)&wf2l, g_wf2l);
    cudaGetSymbolAddress((void**)&wf3h, g_wf3h);
    cudaGetSymbolAddress((void**)&wf3l, g_wf3l);

    constexpr int SM1 = 4096 + 16 * 260 * 8;          // conv1: ~36.5 KB
    constexpr int SM2 = 2 * (1 * 8 * 18 * 18) * 8;    // conv2: ~41.5 KB
    constexpr int SM3 = 2 * (2 * 8 * 10 * 10) * 8;    // conv3: ~25.6 KB
    cudaFuncSetAttribute(conv1_tc, cudaFuncAttributeMaxDynamicSharedMemorySize, SM1);
    cudaFuncSetAttribute(conv_tc_pool<32, 64, 16, 16, 1, 2, 4, 0>,
                         cudaFuncAttributeMaxDynamicSharedMemorySize, SM2);
    cudaFuncSetAttribute(conv_tc_pool<64, 128, 8, 8, 2, 4, 2, 1>,
                         cudaFuncAttributeMaxDynamicSharedMemorySize, SM3);

    // weight pre-split into bf16 fragment order
    wsplit_conv1<<<1, 128>>>(c1w, wf1h, wf1l);
    wsplit_frag_kernel<32, 64><<<(4 * 18 * 32 + 255) / 256, 256>>>(c2w, wf2h, wf2l);
    wsplit_frag_kernel<64, 128><<<(8 * 36 * 32 + 255) / 256, 256>>>(c3w, wf3h, wf3l);

    // conv1 (3->32, 32x32) + maxpool -> [B,32,16,16]  (bf16 TC, quarter-image tiles)
    conv1_tc<<<dim3(1024, 4), 256, SM1>>>(wf1h, wf1l, x, c1b, g1, be1, p1);
    // conv2 (32->64, 16x16) + maxpool -> [B,64,8,8]
    conv_tc_pool<32, 64, 16, 16, 1, 2, 4, 0><<<1024, 256, SM2>>>(wf2h, wf2l, p1, c2b, g2, be2, p2);
    // conv3 (64->128, 8x8) + avgpool -> flatten [B,2048]
    conv_tc_pool<64, 128, 8, 8, 2, 4, 2, 1><<<512, 256, SM3>>>(wf3h, wf3l, p2, c3b, g3, be3, flat);

    fc1_tc_kernel<<<dim3(8, 16), 128>>>(flat, fr1w, fr1b, fc1o);
    tail_kernel<<<128, 256>>>(fc1o, fr2w, fr2b, qw, h1w, h1b, bng, bnb, h2w, h2b, out);
}